// round 12
// baseline (speedup 1.0000x reference)
#include <cuda_runtime.h>
#include <cstdint>

// VoxelPooling: out[n,:] = mean_{k<20} src_feat[idx(n,k), :]
// idx(n,k) = invoxel_map[n,k] (int32), 0 replaced by invoxel_map[n,0].
//
// Inputs: d_in[0] xyz (UNUSED), d_in[1] map int32 [N,20], d_in[2] src_feat f32 [M,16]
// Output: f32 [N,16]
//
// Two sequential passes over disjoint index halves of src_feat (64 MB each).
// Gathers are branchless PREDICATED asm loads (R11: zero wavefronts / zero
// traffic when off).
// R11 post-mortem: regs=32 -> ptxas had ~8 float4 dests -> MLP_eff ~4 ->
// latency equilibrium at ~57% on every unit. R12: stage gathers in chunks of
// 10 with dedicated destination registers so 10 loads are in flight per
// thread before any accumulate; ~64 regs, occ ~50%, in-flight lines/SM ~10x.

#define FUSE_K 20
#define G 10   // gather batch size (10 x float4 dests = 40 regs)

// Predicated 16B gather: returns zeros when !in, performs no memory access.
__device__ __forceinline__ float4 ldg_pred(const float4* p, int in) {
    float4 r;
    asm("{\n\t"
        ".reg .pred q;\n\t"
        "setp.ne.s32 q, %5, 0;\n\t"
        "mov.f32 %0, 0f00000000;\n\t"
        "mov.f32 %1, 0f00000000;\n\t"
        "mov.f32 %2, 0f00000000;\n\t"
        "mov.f32 %3, 0f00000000;\n\t"
        "@q ld.global.nc.v4.f32 {%0,%1,%2,%3}, [%4];\n\t"
        "}"
        : "=f"(r.x), "=f"(r.y), "=f"(r.z), "=f"(r.w)
        : "l"(p), "r"(in));
    return r;
}

template <bool FIRST, bool LAST>
__global__ __launch_bounds__(256) void voxel_pool_pass(
    const int* __restrict__ invoxel_map,   // [N, FUSE_K] int32
    const float4* __restrict__ src_feat,   // [M,4] float4 view of [M,16]
    float4* __restrict__ out,              // [N,4] float4 view of [N,16]
    int N, int lo, int hi)
{
    int t = blockIdx.x * blockDim.x + threadIdx.x;
    int v  = t >> 2;        // voxel
    int cp = t & 3;         // float4 chunk of the 16 channels
    if (v >= N) return;

    // 20 indices via 5x int4 (row stride 80B, 16B aligned). Streaming.
    const int4* m = reinterpret_cast<const int4*>(invoxel_map + (long long)v * FUSE_K);
    int idx[FUSE_K];
#pragma unroll
    for (int q = 0; q < FUSE_K / 4; q++) {
        int4 p = __ldcs(&m[q]);
        idx[q * 4 + 0] = p.x;
        idx[q * 4 + 1] = p.y;
        idx[q * 4 + 2] = p.z;
        idx[q * 4 + 3] = p.w;
    }

    int first = idx[0];
#pragma unroll
    for (int k = 0; k < FUSE_K; k++)
        idx[k] = (idx[k] == 0) ? first : idx[k];

    float4 acc;
    if (FIRST) {
        acc = make_float4(0.f, 0.f, 0.f, 0.f);
    } else {
        acc = __ldcs(&out[(long long)v * 4 + cp]);   // partial sums (streaming)
    }

    // Chunked batched gathers: issue G predicated loads into dedicated
    // registers, THEN accumulate. Forces MLP_eff ~ G per thread.
#pragma unroll
    for (int c = 0; c < FUSE_K / G; c++) {
        float4 f[G];
#pragma unroll
        for (int j = 0; j < G; j++) {
            int id = idx[c * G + j];
            int in = (id >= lo) && (id < hi);
            f[j] = ldg_pred(&src_feat[id * 4 + cp], in);
        }
#pragma unroll
        for (int j = 0; j < G; j++) {
            acc.x += f[j].x;
            acc.y += f[j].y;
            acc.z += f[j].z;
            acc.w += f[j].w;
        }
    }

    if (LAST) {
        const float s = 1.0f / (float)FUSE_K;
        acc.x *= s; acc.y *= s; acc.z *= s; acc.w *= s;
    }
    __stcs(&out[(long long)v * 4 + cp], acc);
}

extern "C" void kernel_launch(void* const* d_in, const int* in_sizes, int n_in,
                              void* d_out, int out_size)
{
    const int*    invoxel_map = (const int*)d_in[1];
    const float4* src_feat    = (const float4*)d_in[2];
    float4*       out         = (float4*)d_out;

    int N = in_sizes[1] / FUSE_K;     // voxels
    int M = in_sizes[2] / 16;         // src_feat rows
    int half = M / 2;

    int threads_needed = N * 4;       // 4 lanes per voxel
    int block = 256;
    int grid  = (threads_needed + block - 1) / block;

    voxel_pool_pass<true,  false><<<grid, block>>>(invoxel_map, src_feat, out, N, 0,    half);
    voxel_pool_pass<false, true ><<<grid, block>>>(invoxel_map, src_feat, out, N, half, M);
}

// round 13
// speedup vs baseline: 1.0014x; 1.0014x over previous
#include <cuda_runtime.h>
#include <cstdint>

// VoxelPooling: out[n,:] = mean_{k<20} src_feat[idx(n,k), :]
// idx(n,k) = invoxel_map[n,k] (int32), 0 replaced by invoxel_map[n,0].
//
// Inputs: d_in[0] xyz (UNUSED), d_in[1] map int32 [N,20], d_in[2] src_feat f32 [M,16]
// Output: f32 [N,16]
//
// R13 experiment: SINGLE pass (no index split), but gathers use PLAIN
// ld.global (default .ca caching / normal L2 insertion priority) instead of
// __ldg/.nc. Hypothesis: .nc loads insert at low L2 priority, which explains
// R2's anomalous 17% L2 hit rate on a table (128 MB) that nearly fits in L2
// (126 MB). Streams (map, out) are evict-first (__ldcs/__stcs) to minimize
// pollution. Body is R2's straight-line 20-unconditional-load loop, which
// measurably drives the memory system at 6.3 TB/s.

#define FUSE_K 20

// Plain (default-policy) 16B global load - NOT .nc
__device__ __forceinline__ float4 ldg_ca(const float4* p) {
    float4 r;
    asm("ld.global.v4.f32 {%0,%1,%2,%3}, [%4];"
        : "=f"(r.x), "=f"(r.y), "=f"(r.z), "=f"(r.w)
        : "l"(p));
    return r;
}

__global__ __launch_bounds__(256) void voxel_pool_kernel(
    const int* __restrict__ invoxel_map,   // [N, FUSE_K] int32
    const float4* __restrict__ src_feat,   // [M,4] float4 view of [M,16]
    float4* __restrict__ out,              // [N,4] float4 view of [N,16]
    int N)
{
    int t = blockIdx.x * blockDim.x + threadIdx.x;
    int v  = t >> 2;        // voxel
    int cp = t & 3;         // float4 chunk of the 16 channels
    if (v >= N) return;

    // 20 indices via 5x int4 (row stride 80B, 16B aligned). Streaming.
    const int4* m = reinterpret_cast<const int4*>(invoxel_map + (long long)v * FUSE_K);
    int idx[FUSE_K];
#pragma unroll
    for (int q = 0; q < FUSE_K / 4; q++) {
        int4 p = __ldcs(&m[q]);
        idx[q * 4 + 0] = p.x;
        idx[q * 4 + 1] = p.y;
        idx[q * 4 + 2] = p.z;
        idx[q * 4 + 3] = p.w;
    }

    int first = idx[0];
#pragma unroll
    for (int k = 0; k < FUSE_K; k++)
        idx[k] = (idx[k] == 0) ? first : idx[k];

    // Straight-line unconditional gathers (deep MLP), default L2 insertion.
    float4 acc = make_float4(0.f, 0.f, 0.f, 0.f);
#pragma unroll
    for (int k = 0; k < FUSE_K; k++) {
        float4 f = ldg_ca(&src_feat[idx[k] * 4 + cp]);
        acc.x += f.x;
        acc.y += f.y;
        acc.z += f.z;
        acc.w += f.w;
    }

    const float s = 1.0f / (float)FUSE_K;
    acc.x *= s; acc.y *= s; acc.z *= s; acc.w *= s;

    __stcs(&out[(long long)v * 4 + cp], acc);
}

extern "C" void kernel_launch(void* const* d_in, const int* in_sizes, int n_in,
                              void* d_out, int out_size)
{
    const int*    invoxel_map = (const int*)d_in[1];
    const float4* src_feat    = (const float4*)d_in[2];
    float4*       out         = (float4*)d_out;

    int N = in_sizes[1] / FUSE_K;     // voxels

    int threads_needed = N * 4;       // 4 lanes per voxel
    int block = 256;
    int grid  = (threads_needed + block - 1) / block;

    voxel_pool_kernel<<<grid, block>>>(invoxel_map, src_feat, out, N);
}